// round 14
// baseline (speedup 1.0000x reference)
#include <cuda_runtime.h>
#include <cuda_fp16.h>
#include <cstdint>

// Problem constants
#define NB 8
#define CI 512
#define CO 512
#define HH 64
#define WW 64
#define DENSE_SCALE 0.04419417382415922f
#define CONV_SCALE  0.014731391274719742f
#define CONV_SCALE2 (1.0f/4608.0f)
#define NT 8192            // total 2x2-output tiles (8 * 32 * 32)

// ---------------- device scratch ----------------
__device__ float  g_style[NB*CI];
__device__ float  g_w2[CO*CI];
__device__ float  g_d[NB*CO];
__device__ __align__(1024) __half g_xs2[(size_t)NB*HH*WW*CI];      // NHWC fp16 (modulated)
__device__ __align__(1024) __half g_U[(size_t)16*CO*CI];           // [p][o][ci]
__device__ __align__(1024) __half g_V[(size_t)16*NT*CI];           // [p][t][ci]

// ---------------- prep kernels ----------------
__global__ void k_style(const float* __restrict__ dl, const float* __restrict__ dw,
                        const float* __restrict__ db) {
    int idx = blockIdx.x * 256 + threadIdx.x;
    int b = idx >> 9, i = idx & 511;
    const float* dlr = dl + b * 512;
    const float* dwr = dw + i * 512;
    float acc = 0.f;
#pragma unroll 8
    for (int d = 0; d < 512; d++) acc = fmaf(dlr[d], dwr[d], acc);
    g_style[idx] = acc * DENSE_SCALE + db[i];
}

// weight transform U = G w G^T (scaled) + w^2 sums for demod
__global__ void k_wino_w(const float* __restrict__ w) {
    int idx = blockIdx.x * 256 + threadIdx.x;   // o*512 + ci
    int o = idx >> 9, ci = idx & 511;
    const float* wp = w + (size_t)idx * 9;
    float g[3][3]; float s2 = 0.f;
#pragma unroll
    for (int r = 0; r < 3; r++)
#pragma unroll
        for (int c = 0; c < 3; c++) {
            float v = wp[r * 3 + c];
            g[r][c] = v; s2 = fmaf(v, v, s2);
        }
    g_w2[idx] = s2;
    float t[4][3];
#pragma unroll
    for (int c = 0; c < 3; c++) {
        t[0][c] = g[0][c];
        t[1][c] = 0.5f * (g[0][c] + g[1][c] + g[2][c]);
        t[2][c] = 0.5f * (g[0][c] - g[1][c] + g[2][c]);
        t[3][c] = g[2][c];
    }
#pragma unroll
    for (int r = 0; r < 4; r++) {
        float u0 = t[r][0];
        float u1 = 0.5f * (t[r][0] + t[r][1] + t[r][2]);
        float u2 = 0.5f * (t[r][0] - t[r][1] + t[r][2]);
        float u3 = t[r][2];
        size_t base = (size_t)o * 512 + ci;
        g_U[(size_t)(r * 4 + 0) * (CO * CI) + base] = __float2half_rn(u0 * CONV_SCALE);
        g_U[(size_t)(r * 4 + 1) * (CO * CI) + base] = __float2half_rn(u1 * CONV_SCALE);
        g_U[(size_t)(r * 4 + 2) * (CO * CI) + base] = __float2half_rn(u2 * CONV_SCALE);
        g_U[(size_t)(r * 4 + 3) * (CO * CI) + base] = __float2half_rn(u3 * CONV_SCALE);
    }
}

__global__ void k_demod() {
    int idx = blockIdx.x * 256 + threadIdx.x;
    int b = idx >> 9, o = idx & 511;
    const float* w2r = g_w2 + o * 512;
    const float* sr  = g_style + b * 512;
    float acc = 0.f;
#pragma unroll 8
    for (int i = 0; i < 512; i++) { float s = sr[i]; acc = fmaf(w2r[i], s * s, acc); }
    g_d[idx] = rsqrtf(acc * CONV_SCALE2 + 1e-8f);
}

// NCHW fp32 -> NHWC fp16 (modulated), float4 loads. grid (16,64,8), 256 thr.
__global__ void k_xs_nhwc(const float* __restrict__ x) {
    __shared__ __half sm[64][40];
    int b = blockIdx.z, h = blockIdx.y, c0 = blockIdx.x * 32;
    int t = threadIdx.x;
    int ci = t >> 3, q = t & 7;
    float s = g_style[b * 512 + c0 + ci];
    const float* src = x + (((size_t)b * 512 + c0 + ci) * 64 + h) * 64;
    float4 v0 = *(const float4*)(src + q * 4);
    float4 v1 = *(const float4*)(src + 32 + q * 4);
    int w0 = q * 4;
    sm[w0 + 0][ci] = __float2half_rn(v0.x * s);
    sm[w0 + 1][ci] = __float2half_rn(v0.y * s);
    sm[w0 + 2][ci] = __float2half_rn(v0.z * s);
    sm[w0 + 3][ci] = __float2half_rn(v0.w * s);
    sm[w0 + 32][ci] = __float2half_rn(v1.x * s);
    sm[w0 + 33][ci] = __float2half_rn(v1.y * s);
    sm[w0 + 34][ci] = __float2half_rn(v1.z * s);
    sm[w0 + 35][ci] = __float2half_rn(v1.w * s);
    __syncthreads();
    int w = t >> 2, qq = t & 3;
    uint4 val = *(const uint4*)&sm[w][qq * 8];
    *(uint4*)&g_xs2[(((size_t)b * 64 + h) * 64 + w) * 512 + c0 + qq * 8] = val;
}

// input transform: V = B^T d B per channel pair. grid 8192 blocks, 256 thr.
__global__ void k_wino_in() {
    int t = blockIdx.x;
    int b = t >> 10, ty = (t >> 5) & 31, tx = t & 31;
    int ci = threadIdx.x * 2;
    const __half* xb = g_xs2 + ((size_t)b * 4096) * 512 + ci;

    float2 d[4][4];
#pragma unroll
    for (int i = 0; i < 4; i++) {
        int r = 2 * ty - 1 + i;
        bool rok = (unsigned)r < 64u;
#pragma unroll
        for (int j = 0; j < 4; j++) {
            int c = 2 * tx - 1 + j;
            if (rok && (unsigned)c < 64u) {
                __half2 h = *(const __half2*)(xb + (size_t)(r * 64 + c) * 512);
                d[i][j] = __half22float2(h);
            } else {
                d[i][j] = make_float2(0.f, 0.f);
            }
        }
    }
    float2 u[4][4];
#pragma unroll
    for (int j = 0; j < 4; j++) {
        u[0][j].x = d[0][j].x - d[2][j].x;  u[0][j].y = d[0][j].y - d[2][j].y;
        u[1][j].x = d[1][j].x + d[2][j].x;  u[1][j].y = d[1][j].y + d[2][j].y;
        u[2][j].x = d[2][j].x - d[1][j].x;  u[2][j].y = d[2][j].y - d[1][j].y;
        u[3][j].x = d[1][j].x - d[3][j].x;  u[3][j].y = d[1][j].y - d[3][j].y;
    }
#pragma unroll
    for (int i = 0; i < 4; i++) {
        float2 v0, v1, v2, v3;
        v0.x = u[i][0].x - u[i][2].x;  v0.y = u[i][0].y - u[i][2].y;
        v1.x = u[i][1].x + u[i][2].x;  v1.y = u[i][1].y + u[i][2].y;
        v2.x = u[i][2].x - u[i][1].x;  v2.y = u[i][2].y - u[i][1].y;
        v3.x = u[i][1].x - u[i][3].x;  v3.y = u[i][1].y - u[i][3].y;
        size_t base = (size_t)t * 512 + ci;
        *(__half2*)&g_V[(size_t)(i * 4 + 0) * (NT * CI) + base] = __floats2half2_rn(v0.x, v0.y);
        *(__half2*)&g_V[(size_t)(i * 4 + 1) * (NT * CI) + base] = __floats2half2_rn(v1.x, v1.y);
        *(__half2*)&g_V[(size_t)(i * 4 + 2) * (NT * CI) + base] = __floats2half2_rn(v2.x, v2.y);
        *(__half2*)&g_V[(size_t)(i * 4 + 3) * (NT * CI) + base] = __floats2half2_rn(v3.x, v3.y);
    }
}

// ---------------- fused Winograd GEMM (all 16 p) + inverse + demod ----------------
__device__ __forceinline__ uint32_t s2u(const void* p) {
    return (uint32_t)__cvta_generic_to_shared(p);
}
__device__ __forceinline__ void ldsm4(uint32_t* r, uint32_t a) {
    asm volatile("ldmatrix.sync.aligned.m8n8.x4.shared.b16 {%0,%1,%2,%3}, [%4];"
                 : "=r"(r[0]), "=r"(r[1]), "=r"(r[2]), "=r"(r[3]) : "r"(a));
}
__device__ __forceinline__ void mma16816(float* c, const uint32_t* a, uint32_t b0, uint32_t b1) {
    asm volatile("mma.sync.aligned.m16n8k16.row.col.f32.f16.f16.f32 "
                 "{%0,%1,%2,%3}, {%4,%5,%6,%7}, {%8,%9}, {%0,%1,%2,%3};"
                 : "+f"(c[0]), "+f"(c[1]), "+f"(c[2]), "+f"(c[3])
                 : "r"(a[0]), "r"(a[1]), "r"(a[2]), "r"(a[3]), "r"(b0), "r"(b1));
}
__device__ __forceinline__ void cpa16(uint32_t d, const void* s) {
    asm volatile("cp.async.cg.shared.global [%0], [%1], 16;"
                 :: "r"(d), "l"(s) : "memory");
}
__device__ __forceinline__ void cp_commit() {
    asm volatile("cp.async.commit_group;" ::: "memory");
}
__device__ __forceinline__ void cp_wait1() {
    asm volatile("cp.async.wait_group 1;" ::: "memory");
}

// stage = U(64 o x 80B) + V(64 t x 80B); ring of 3
#define WGA_BUF 5120
#define WGSTAGE (2 * WGA_BUF)
#define WGSM    (3 * WGSTAGE)

// CTA = 64 o x 64 t, all 16 p. grid (8 ob, 128 tb). 256 thr, 8 warps:
// warp = 32 o (wm) x 16 t (wt). 256 pipeline stages (p major, ci-chunk minor).
__global__ __launch_bounds__(256, 1) void k_wgemm(float* __restrict__ out) {
    extern __shared__ char smraw[];
    int tid = threadIdx.x, lane = tid & 31, warp = tid >> 5;
    int wm = warp & 1, wt = warp >> 1;
    int ob = blockIdx.x * 64;
    int tb = blockIdx.y * 64;

    const __half* U0 = g_U + (size_t)ob * 512;
    const __half* V0 = g_V + (size_t)tb * 512;

    float acc[2][2][4];          // per-p GEMM accums: [o-16 half][t-8 half][frag]
    float outv[2][2][4][4];      // output accums: [...][frag][dy*2+dx]
#pragma unroll
    for (int i = 0; i < 2; i++)
#pragma unroll
        for (int j = 0; j < 2; j++)
#pragma unroll
            for (int k = 0; k < 4; k++) {
                acc[i][j][k] = 0.f;
#pragma unroll
                for (int e = 0; e < 4; e++) outv[i][j][k][e] = 0.f;
            }

    auto issue = [&](int s) {
        int p = s >> 4, ch = s & 15;
        char* st = smraw + (s % 3) * WGSTAGE;
        int row = tid >> 2, q = tid & 3;
        size_t off = (size_t)row * 512 + ch * 32 + q * 8;
        cpa16(s2u(st + row * 80 + q * 16), U0 + (size_t)p * (CO * CI) + off);
        cpa16(s2u(st + WGA_BUF + row * 80 + q * 16), V0 + (size_t)p * (NT * CI) + off);
    };

    issue(0); cp_commit();
    issue(1); cp_commit();

    uint32_t aLane = (uint32_t)((wm * 32 + (lane & 15)) * 80 + ((lane >> 4) << 4));
    uint32_t bLane = (uint32_t)((wt * 16 + (lane & 15)) * 80 + ((lane >> 4) << 4));

    for (int s = 0; s < 256; ++s) {
        cp_wait1();
        __syncthreads();
        if (s + 2 < 256) issue(s + 2);
        cp_commit();

        char* st = smraw + (s % 3) * WGSTAGE;
        uint32_t aB = s2u(st) + aLane;
        uint32_t bB = s2u(st + WGA_BUF) + bLane;

#pragma unroll
        for (int k0 = 0; k0 < 2; k0++) {
            uint32_t a0[4], a1[4], bf[4];
            ldsm4(a0, aB + k0 * 32);               // o 0-15 (of warp's 32)
            ldsm4(a1, aB + 16 * 80 + k0 * 32);     // o 16-31
            ldsm4(bf, bB + k0 * 32);               // t 0-15, k lo/hi tiles
#pragma unroll
            for (int j = 0; j < 2; j++) {
                mma16816(acc[0][j], a0, bf[j], bf[2 + j]);
                mma16816(acc[1][j], a1, bf[j], bf[2 + j]);
            }
        }

        if ((s & 15) == 15) {     // p complete: inverse-transform accumulate
            int p = s >> 4;
            int r = p >> 2, cc = p & 3;
            float a0r = (r == 3) ? 0.f : 1.f;
            float a1r = (r == 0) ? 0.f : ((r == 1) ? 1.f : -1.f);
            float a0c = (cc == 3) ? 0.f : 1.f;
            float a1c = (cc == 0) ? 0.f : ((cc == 1) ? 1.f : -1.f);
            float c00 = a0r * a0c, c01 = a0r * a1c, c10 = a1r * a0c, c11 = a1r * a1c;
#pragma unroll
            for (int i = 0; i < 2; i++)
#pragma unroll
                for (int j = 0; j < 2; j++)
#pragma unroll
                    for (int k = 0; k < 4; k++) {
                        float v = acc[i][j][k];
                        outv[i][j][k][0] = fmaf(c00, v, outv[i][j][k][0]);
                        outv[i][j][k][1] = fmaf(c01, v, outv[i][j][k][1]);
                        outv[i][j][k][2] = fmaf(c10, v, outv[i][j][k][2]);
                        outv[i][j][k][3] = fmaf(c11, v, outv[i][j][k][3]);
                        acc[i][j][k] = 0.f;
                    }
        }
    }

    // ---- epilogue: demod + NCHW store (float4 per (o,dy)) ----
    int tl = tb + wt * 16 + (lane & 3) * 2;   // global tile idx (even)
    int b  = tl >> 10;
#pragma unroll
    for (int i = 0; i < 2; i++) {
#pragma unroll
        for (int j = 0; j < 2; j++) {
            int tj = j * 8;                    // t offset for this j-block
            int tyj = ((tl + tj) >> 5) & 31;
            int txj = (tl + tj) & 31;
#pragma unroll
            for (int mh = 0; mh < 2; mh++) {
                int o = ob + wm * 32 + i * 16 + (lane >> 2) + mh * 8;
                float ds = g_d[b * 512 + o];
                float* obase = out + ((size_t)(b * 512 + o) * 64) * 64;
#pragma unroll
                for (int dy = 0; dy < 2; dy++) {
                    float4 v;
                    v.x = outv[i][j][2 * mh + 0][dy * 2 + 0] * ds;
                    v.y = outv[i][j][2 * mh + 0][dy * 2 + 1] * ds;
                    v.z = outv[i][j][2 * mh + 1][dy * 2 + 0] * ds;
                    v.w = outv[i][j][2 * mh + 1][dy * 2 + 1] * ds;
                    *(float4*)(obase + (size_t)(2 * tyj + dy) * 64 + 2 * txj) = v;
                }
            }
        }
    }
}

// ---------------- launcher ----------------
extern "C" void kernel_launch(void* const* d_in, const int* in_sizes, int n_in,
                              void* d_out, int out_size) {
    const float* x  = (const float*)d_in[0];
    const float* dl = (const float*)d_in[1];
    const float* w  = (const float*)d_in[2];
    const float* dw = (const float*)d_in[3];
    const float* db = (const float*)d_in[4];
    float* out = (float*)d_out;

    k_style<<<16, 256>>>(dl, dw, db);
    k_wino_w<<<1024, 256>>>(w);
    k_demod<<<16, 256>>>();
    k_xs_nhwc<<<dim3(16, 64, 8), 256>>>(x);
    k_wino_in<<<8192, 256>>>();

    cudaFuncSetAttribute(k_wgemm, cudaFuncAttributeMaxDynamicSharedMemorySize, WGSM);
    k_wgemm<<<dim3(8, 128), 256, WGSM>>>(out);
}

// round 15
// speedup vs baseline: 1.0249x; 1.0249x over previous
#include <cuda_runtime.h>
#include <cuda_fp16.h>
#include <cstdint>

// Problem constants
#define NB 8
#define CI 512
#define CO 512
#define HH 64
#define WW 64
#define DENSE_SCALE 0.04419417382415922f
#define CONV_SCALE  0.014731391274719742f
#define CONV_SCALE2 (1.0f/4608.0f)
#define NT 8192            // total 2x2-output tiles (8 * 32 * 32)

// ---------------- device scratch ----------------
__device__ float  g_style[NB*CI];
__device__ float  g_w2[CO*CI];
__device__ float  g_d[NB*CO];
__device__ __align__(1024) __half g_xs2[(size_t)NB*HH*WW*CI];      // NHWC fp16 (modulated)
__device__ __align__(1024) __half g_U[(size_t)16*CO*CI];           // [p][o][ci]
__device__ __align__(1024) __half g_V[(size_t)16*NT*CI];           // [p][t][ci]

// ---------------- prep kernels ----------------
__global__ void k_style(const float* __restrict__ dl, const float* __restrict__ dw,
                        const float* __restrict__ db) {
    int idx = blockIdx.x * 256 + threadIdx.x;
    int b = idx >> 9, i = idx & 511;
    const float* dlr = dl + b * 512;
    const float* dwr = dw + i * 512;
    float acc = 0.f;
#pragma unroll 8
    for (int d = 0; d < 512; d++) acc = fmaf(dlr[d], dwr[d], acc);
    g_style[idx] = acc * DENSE_SCALE + db[i];
}

// weight transform U = G w G^T (scaled) + w^2 sums for demod
__global__ void k_wino_w(const float* __restrict__ w) {
    int idx = blockIdx.x * 256 + threadIdx.x;   // o*512 + ci
    int o = idx >> 9, ci = idx & 511;
    const float* wp = w + (size_t)idx * 9;
    float g[3][3]; float s2 = 0.f;
#pragma unroll
    for (int r = 0; r < 3; r++)
#pragma unroll
        for (int c = 0; c < 3; c++) {
            float v = wp[r * 3 + c];
            g[r][c] = v; s2 = fmaf(v, v, s2);
        }
    g_w2[idx] = s2;
    float t[4][3];
#pragma unroll
    for (int c = 0; c < 3; c++) {
        t[0][c] = g[0][c];
        t[1][c] = 0.5f * (g[0][c] + g[1][c] + g[2][c]);
        t[2][c] = 0.5f * (g[0][c] - g[1][c] + g[2][c]);
        t[3][c] = g[2][c];
    }
#pragma unroll
    for (int r = 0; r < 4; r++) {
        float u0 = t[r][0];
        float u1 = 0.5f * (t[r][0] + t[r][1] + t[r][2]);
        float u2 = 0.5f * (t[r][0] - t[r][1] + t[r][2]);
        float u3 = t[r][2];
        size_t base = (size_t)o * 512 + ci;
        g_U[(size_t)(r * 4 + 0) * (CO * CI) + base] = __float2half_rn(u0 * CONV_SCALE);
        g_U[(size_t)(r * 4 + 1) * (CO * CI) + base] = __float2half_rn(u1 * CONV_SCALE);
        g_U[(size_t)(r * 4 + 2) * (CO * CI) + base] = __float2half_rn(u2 * CONV_SCALE);
        g_U[(size_t)(r * 4 + 3) * (CO * CI) + base] = __float2half_rn(u3 * CONV_SCALE);
    }
}

__global__ void k_demod() {
    int idx = blockIdx.x * 256 + threadIdx.x;
    int b = idx >> 9, o = idx & 511;
    const float* w2r = g_w2 + o * 512;
    const float* sr  = g_style + b * 512;
    float acc = 0.f;
#pragma unroll 8
    for (int i = 0; i < 512; i++) { float s = sr[i]; acc = fmaf(w2r[i], s * s, acc); }
    g_d[idx] = rsqrtf(acc * CONV_SCALE2 + 1e-8f);
}

// NCHW fp32 -> NHWC fp16 (modulated), float4 loads. grid (16,64,8), 256 thr.
__global__ void k_xs_nhwc(const float* __restrict__ x) {
    __shared__ __half sm[64][40];
    int b = blockIdx.z, h = blockIdx.y, c0 = blockIdx.x * 32;
    int t = threadIdx.x;
    int ci = t >> 3, q = t & 7;
    float s = g_style[b * 512 + c0 + ci];
    const float* src = x + (((size_t)b * 512 + c0 + ci) * 64 + h) * 64;
    float4 v0 = *(const float4*)(src + q * 4);
    float4 v1 = *(const float4*)(src + 32 + q * 4);
    int w0 = q * 4;
    sm[w0 + 0][ci] = __float2half_rn(v0.x * s);
    sm[w0 + 1][ci] = __float2half_rn(v0.y * s);
    sm[w0 + 2][ci] = __float2half_rn(v0.z * s);
    sm[w0 + 3][ci] = __float2half_rn(v0.w * s);
    sm[w0 + 32][ci] = __float2half_rn(v1.x * s);
    sm[w0 + 33][ci] = __float2half_rn(v1.y * s);
    sm[w0 + 34][ci] = __float2half_rn(v1.z * s);
    sm[w0 + 35][ci] = __float2half_rn(v1.w * s);
    __syncthreads();
    int w = t >> 2, qq = t & 3;
    uint4 val = *(const uint4*)&sm[w][qq * 8];
    *(uint4*)&g_xs2[(((size_t)b * 64 + h) * 64 + w) * 512 + c0 + qq * 8] = val;
}

// input transform: V = B^T d B per channel pair. grid 8192 blocks, 256 thr.
__global__ void k_wino_in() {
    int t = blockIdx.x;
    int b = t >> 10, ty = (t >> 5) & 31, tx = t & 31;
    int ci = threadIdx.x * 2;
    const __half* xb = g_xs2 + ((size_t)b * 4096) * 512 + ci;

    float2 d[4][4];
#pragma unroll
    for (int i = 0; i < 4; i++) {
        int r = 2 * ty - 1 + i;
        bool rok = (unsigned)r < 64u;
#pragma unroll
        for (int j = 0; j < 4; j++) {
            int c = 2 * tx - 1 + j;
            if (rok && (unsigned)c < 64u) {
                __half2 h = *(const __half2*)(xb + (size_t)(r * 64 + c) * 512);
                d[i][j] = __half22float2(h);
            } else {
                d[i][j] = make_float2(0.f, 0.f);
            }
        }
    }
    float2 u[4][4];
#pragma unroll
    for (int j = 0; j < 4; j++) {
        u[0][j].x = d[0][j].x - d[2][j].x;  u[0][j].y = d[0][j].y - d[2][j].y;
        u[1][j].x = d[1][j].x + d[2][j].x;  u[1][j].y = d[1][j].y + d[2][j].y;
        u[2][j].x = d[2][j].x - d[1][j].x;  u[2][j].y = d[2][j].y - d[1][j].y;
        u[3][j].x = d[1][j].x - d[3][j].x;  u[3][j].y = d[1][j].y - d[3][j].y;
    }
#pragma unroll
    for (int i = 0; i < 4; i++) {
        float2 v0, v1, v2, v3;
        v0.x = u[i][0].x - u[i][2].x;  v0.y = u[i][0].y - u[i][2].y;
        v1.x = u[i][1].x + u[i][2].x;  v1.y = u[i][1].y + u[i][2].y;
        v2.x = u[i][2].x - u[i][1].x;  v2.y = u[i][2].y - u[i][1].y;
        v3.x = u[i][1].x - u[i][3].x;  v3.y = u[i][1].y - u[i][3].y;
        size_t base = (size_t)t * 512 + ci;
        *(__half2*)&g_V[(size_t)(i * 4 + 0) * (NT * CI) + base] = __floats2half2_rn(v0.x, v0.y);
        *(__half2*)&g_V[(size_t)(i * 4 + 1) * (NT * CI) + base] = __floats2half2_rn(v1.x, v1.y);
        *(__half2*)&g_V[(size_t)(i * 4 + 2) * (NT * CI) + base] = __floats2half2_rn(v2.x, v2.y);
        *(__half2*)&g_V[(size_t)(i * 4 + 3) * (NT * CI) + base] = __floats2half2_rn(v3.x, v3.y);
    }
}

// ---------------- fused Winograd GEMM (all 16 p) + inverse + demod ----------------
__device__ __forceinline__ uint32_t s2u(const void* p) {
    return (uint32_t)__cvta_generic_to_shared(p);
}
__device__ __forceinline__ void ldsm4(uint32_t* r, uint32_t a) {
    asm volatile("ldmatrix.sync.aligned.m8n8.x4.shared.b16 {%0,%1,%2,%3}, [%4];"
                 : "=r"(r[0]), "=r"(r[1]), "=r"(r[2]), "=r"(r[3]) : "r"(a));
}
__device__ __forceinline__ void mma16816(float* c, const uint32_t* a, uint32_t b0, uint32_t b1) {
    asm volatile("mma.sync.aligned.m16n8k16.row.col.f32.f16.f16.f32 "
                 "{%0,%1,%2,%3}, {%4,%5,%6,%7}, {%8,%9}, {%0,%1,%2,%3};"
                 : "+f"(c[0]), "+f"(c[1]), "+f"(c[2]), "+f"(c[3])
                 : "r"(a[0]), "r"(a[1]), "r"(a[2]), "r"(a[3]), "r"(b0), "r"(b1));
}
__device__ __forceinline__ void cpa16(uint32_t d, const void* s) {
    asm volatile("cp.async.cg.shared.global [%0], [%1], 16;"
                 :: "r"(d), "l"(s) : "memory");
}
__device__ __forceinline__ void cp_commit() {
    asm volatile("cp.async.commit_group;" ::: "memory");
}
__device__ __forceinline__ void cp_wait1() {
    asm volatile("cp.async.wait_group 1;" ::: "memory");
}

// stage = U(64 o x 80B) + V(64 t x 80B); ring of 3
#define WGA_BUF 5120
#define WGSTAGE (2 * WGA_BUF)
#define WGSM    (3 * WGSTAGE)

// CTA = 64 o x 64 t, all 16 p. grid (8 ob, 128 tb). 256 thr, 8 warps:
// warp = 32 o (wm) x 16 t (wt). 256 pipeline stages (p major, ci-chunk minor).
// launch_bounds(256,2): cap 128 regs -> 2 CTAs/SM to hide per-stage overhead.
__global__ __launch_bounds__(256, 2) void k_wgemm(float* __restrict__ out) {
    extern __shared__ char smraw[];
    int tid = threadIdx.x, lane = tid & 31, warp = tid >> 5;
    int wm = warp & 1, wt = warp >> 1;
    int ob = blockIdx.x * 64;
    int tb = blockIdx.y * 64;

    const __half* U0 = g_U + (size_t)ob * 512;
    const __half* V0 = g_V + (size_t)tb * 512;

    float acc[2][2][4];          // per-p GEMM accums: [o-16 half][t-8 half][frag]
    float outv[2][2][4][4];      // output accums: [...][frag][dy*2+dx]
#pragma unroll
    for (int i = 0; i < 2; i++)
#pragma unroll
        for (int j = 0; j < 2; j++)
#pragma unroll
            for (int k = 0; k < 4; k++) {
                acc[i][j][k] = 0.f;
#pragma unroll
                for (int e = 0; e < 4; e++) outv[i][j][k][e] = 0.f;
            }

    auto issue = [&](int s) {
        int p = s >> 4, ch = s & 15;
        char* st = smraw + (s % 3) * WGSTAGE;
        int row = tid >> 2, q = tid & 3;
        size_t off = (size_t)row * 512 + ch * 32 + q * 8;
        cpa16(s2u(st + row * 80 + q * 16), U0 + (size_t)p * (CO * CI) + off);
        cpa16(s2u(st + WGA_BUF + row * 80 + q * 16), V0 + (size_t)p * (NT * CI) + off);
    };

    issue(0); cp_commit();
    issue(1); cp_commit();

    uint32_t aLane = (uint32_t)((wm * 32 + (lane & 15)) * 80 + ((lane >> 4) << 4));
    uint32_t bLane = (uint32_t)((wt * 16 + (lane & 15)) * 80 + ((lane >> 4) << 4));

    for (int s = 0; s < 256; ++s) {
        cp_wait1();
        __syncthreads();
        if (s + 2 < 256) issue(s + 2);
        cp_commit();

        char* st = smraw + (s % 3) * WGSTAGE;
        uint32_t aB = s2u(st) + aLane;
        uint32_t bB = s2u(st + WGA_BUF) + bLane;

#pragma unroll
        for (int k0 = 0; k0 < 2; k0++) {
            uint32_t a0[4], a1[4], bf[4];
            ldsm4(a0, aB + k0 * 32);               // o 0-15 (of warp's 32)
            ldsm4(a1, aB + 16 * 80 + k0 * 32);     // o 16-31
            ldsm4(bf, bB + k0 * 32);               // t 0-15, k lo/hi tiles
#pragma unroll
            for (int j = 0; j < 2; j++) {
                mma16816(acc[0][j], a0, bf[j], bf[2 + j]);
                mma16816(acc[1][j], a1, bf[j], bf[2 + j]);
            }
        }

        if ((s & 15) == 15) {     // p complete: inverse-transform accumulate
            int p = s >> 4;
            int r = p >> 2, cc = p & 3;
            float a0r = (r == 3) ? 0.f : 1.f;
            float a1r = (r == 0) ? 0.f : ((r == 1) ? 1.f : -1.f);
            float a0c = (cc == 3) ? 0.f : 1.f;
            float a1c = (cc == 0) ? 0.f : ((cc == 1) ? 1.f : -1.f);
            float c00 = a0r * a0c, c01 = a0r * a1c, c10 = a1r * a0c, c11 = a1r * a1c;
#pragma unroll
            for (int i = 0; i < 2; i++)
#pragma unroll
                for (int j = 0; j < 2; j++)
#pragma unroll
                    for (int k = 0; k < 4; k++) {
                        float v = acc[i][j][k];
                        outv[i][j][k][0] = fmaf(c00, v, outv[i][j][k][0]);
                        outv[i][j][k][1] = fmaf(c01, v, outv[i][j][k][1]);
                        outv[i][j][k][2] = fmaf(c10, v, outv[i][j][k][2]);
                        outv[i][j][k][3] = fmaf(c11, v, outv[i][j][k][3]);
                        acc[i][j][k] = 0.f;
                    }
        }
    }

    // ---- epilogue: demod + NCHW store (float4 per (o,dy)) ----
    int tl = tb + wt * 16 + (lane & 3) * 2;   // global tile idx (even)
    int b  = tl >> 10;
#pragma unroll
    for (int i = 0; i < 2; i++) {
#pragma unroll
        for (int j = 0; j < 2; j++) {
            int tj = j * 8;                    // t offset for this j-block
            int tyj = ((tl + tj) >> 5) & 31;
            int txj = (tl + tj) & 31;
#pragma unroll
            for (int mh = 0; mh < 2; mh++) {
                int o = ob + wm * 32 + i * 16 + (lane >> 2) + mh * 8;
                float ds = g_d[b * 512 + o];
                float* obase = out + ((size_t)(b * 512 + o) * 64) * 64;
#pragma unroll
                for (int dy = 0; dy < 2; dy++) {
                    float4 v;
                    v.x = outv[i][j][2 * mh + 0][dy * 2 + 0] * ds;
                    v.y = outv[i][j][2 * mh + 0][dy * 2 + 1] * ds;
                    v.z = outv[i][j][2 * mh + 1][dy * 2 + 0] * ds;
                    v.w = outv[i][j][2 * mh + 1][dy * 2 + 1] * ds;
                    *(float4*)(obase + (size_t)(2 * tyj + dy) * 64 + 2 * txj) = v;
                }
            }
        }
    }
}

// ---------------- launcher ----------------
extern "C" void kernel_launch(void* const* d_in, const int* in_sizes, int n_in,
                              void* d_out, int out_size) {
    const float* x  = (const float*)d_in[0];
    const float* dl = (const float*)d_in[1];
    const float* w  = (const float*)d_in[2];
    const float* dw = (const float*)d_in[3];
    const float* db = (const float*)d_in[4];
    float* out = (float*)d_out;

    k_style<<<16, 256>>>(dl, dw, db);
    k_wino_w<<<1024, 256>>>(w);
    k_demod<<<16, 256>>>();
    k_xs_nhwc<<<dim3(16, 64, 8), 256>>>(x);
    k_wino_in<<<8192, 256>>>();

    cudaFuncSetAttribute(k_wgemm, cudaFuncAttributeMaxDynamicSharedMemorySize, WGSM);
    k_wgemm<<<dim3(8, 128), 256, WGSM>>>(out);
}

// round 17
// speedup vs baseline: 1.2029x; 1.1737x over previous
#include <cuda_runtime.h>
#include <cuda_fp16.h>
#include <cstdint>

// Problem constants
#define NB 8
#define CI 512
#define CO 512
#define HH 64
#define WW 64
#define DENSE_SCALE 0.04419417382415922f
#define CONV_SCALE  0.014731391274719742f
#define CONV_SCALE2 (1.0f/4608.0f)
#define NT 8192            // total 2x2-output tiles (8 * 32 * 32)

// ---------------- device scratch ----------------
__device__ float  g_style[NB*CI];
__device__ float  g_w2[CO*CI];
__device__ float  g_d[NB*CO];
__device__ __align__(1024) __half g_xs2[(size_t)NB*HH*WW*CI];      // NHWC fp16 (modulated)
__device__ __align__(1024) __half g_U[(size_t)16*CO*CI];           // [p][o][ci]
__device__ __align__(1024) __half g_V[(size_t)16*NT*CI];           // [p][t][ci]
__device__ __align__(1024) __half g_M[(size_t)16*NT*CO];           // [p][t][o]  fp16

// ---------------- prep kernels ----------------
__global__ void k_style(const float* __restrict__ dl, const float* __restrict__ dw,
                        const float* __restrict__ db) {
    int idx = blockIdx.x * 256 + threadIdx.x;
    int b = idx >> 9, i = idx & 511;
    const float* dlr = dl + b * 512;
    const float* dwr = dw + i * 512;
    float acc = 0.f;
#pragma unroll 8
    for (int d = 0; d < 512; d++) acc = fmaf(dlr[d], dwr[d], acc);
    g_style[idx] = acc * DENSE_SCALE + db[i];
}

// weight transform U = G w G^T (scaled) + w^2 sums for demod
__global__ void k_wino_w(const float* __restrict__ w) {
    int idx = blockIdx.x * 256 + threadIdx.x;   // o*512 + ci
    int o = idx >> 9, ci = idx & 511;
    const float* wp = w + (size_t)idx * 9;
    float g[3][3]; float s2 = 0.f;
#pragma unroll
    for (int r = 0; r < 3; r++)
#pragma unroll
        for (int c = 0; c < 3; c++) {
            float v = wp[r * 3 + c];
            g[r][c] = v; s2 = fmaf(v, v, s2);
        }
    g_w2[idx] = s2;
    float t[4][3];
#pragma unroll
    for (int c = 0; c < 3; c++) {
        t[0][c] = g[0][c];
        t[1][c] = 0.5f * (g[0][c] + g[1][c] + g[2][c]);
        t[2][c] = 0.5f * (g[0][c] - g[1][c] + g[2][c]);
        t[3][c] = g[2][c];
    }
#pragma unroll
    for (int r = 0; r < 4; r++) {
        float u0 = t[r][0];
        float u1 = 0.5f * (t[r][0] + t[r][1] + t[r][2]);
        float u2 = 0.5f * (t[r][0] - t[r][1] + t[r][2]);
        float u3 = t[r][2];
        size_t base = (size_t)o * 512 + ci;
        g_U[(size_t)(r * 4 + 0) * (CO * CI) + base] = __float2half_rn(u0 * CONV_SCALE);
        g_U[(size_t)(r * 4 + 1) * (CO * CI) + base] = __float2half_rn(u1 * CONV_SCALE);
        g_U[(size_t)(r * 4 + 2) * (CO * CI) + base] = __float2half_rn(u2 * CONV_SCALE);
        g_U[(size_t)(r * 4 + 3) * (CO * CI) + base] = __float2half_rn(u3 * CONV_SCALE);
    }
}

__global__ void k_demod() {
    int idx = blockIdx.x * 256 + threadIdx.x;
    int b = idx >> 9, o = idx & 511;
    const float* w2r = g_w2 + o * 512;
    const float* sr  = g_style + b * 512;
    float acc = 0.f;
#pragma unroll 8
    for (int i = 0; i < 512; i++) { float s = sr[i]; acc = fmaf(w2r[i], s * s, acc); }
    g_d[idx] = rsqrtf(acc * CONV_SCALE2 + 1e-8f);
}

// NCHW fp32 -> NHWC fp16 (modulated), float4 loads. grid (16,64,8), 256 thr.
__global__ void k_xs_nhwc(const float* __restrict__ x) {
    __shared__ __half sm[64][40];
    int b = blockIdx.z, h = blockIdx.y, c0 = blockIdx.x * 32;
    int t = threadIdx.x;
    int ci = t >> 3, q = t & 7;
    float s = g_style[b * 512 + c0 + ci];
    const float* src = x + (((size_t)b * 512 + c0 + ci) * 64 + h) * 64;
    float4 v0 = *(const float4*)(src + q * 4);
    float4 v1 = *(const float4*)(src + 32 + q * 4);
    int w0 = q * 4;
    sm[w0 + 0][ci] = __float2half_rn(v0.x * s);
    sm[w0 + 1][ci] = __float2half_rn(v0.y * s);
    sm[w0 + 2][ci] = __float2half_rn(v0.z * s);
    sm[w0 + 3][ci] = __float2half_rn(v0.w * s);
    sm[w0 + 32][ci] = __float2half_rn(v1.x * s);
    sm[w0 + 33][ci] = __float2half_rn(v1.y * s);
    sm[w0 + 34][ci] = __float2half_rn(v1.z * s);
    sm[w0 + 35][ci] = __float2half_rn(v1.w * s);
    __syncthreads();
    int w = t >> 2, qq = t & 3;
    uint4 val = *(const uint4*)&sm[w][qq * 8];
    *(uint4*)&g_xs2[(((size_t)b * 64 + h) * 64 + w) * 512 + c0 + qq * 8] = val;
}

// input transform: V = B^T d B per channel pair. grid 8192 blocks, 256 thr.
__global__ void k_wino_in() {
    int t = blockIdx.x;
    int b = t >> 10, ty = (t >> 5) & 31, tx = t & 31;
    int ci = threadIdx.x * 2;
    const __half* xb = g_xs2 + ((size_t)b * 4096) * 512 + ci;

    float2 d[4][4];
#pragma unroll
    for (int i = 0; i < 4; i++) {
        int r = 2 * ty - 1 + i;
        bool rok = (unsigned)r < 64u;
#pragma unroll
        for (int j = 0; j < 4; j++) {
            int c = 2 * tx - 1 + j;
            if (rok && (unsigned)c < 64u) {
                __half2 h = *(const __half2*)(xb + (size_t)(r * 64 + c) * 512);
                d[i][j] = __half22float2(h);
            } else {
                d[i][j] = make_float2(0.f, 0.f);
            }
        }
    }
    float2 u[4][4];
#pragma unroll
    for (int j = 0; j < 4; j++) {
        u[0][j].x = d[0][j].x - d[2][j].x;  u[0][j].y = d[0][j].y - d[2][j].y;
        u[1][j].x = d[1][j].x + d[2][j].x;  u[1][j].y = d[1][j].y + d[2][j].y;
        u[2][j].x = d[2][j].x - d[1][j].x;  u[2][j].y = d[2][j].y - d[1][j].y;
        u[3][j].x = d[1][j].x - d[3][j].x;  u[3][j].y = d[1][j].y - d[3][j].y;
    }
#pragma unroll
    for (int i = 0; i < 4; i++) {
        float2 v0, v1, v2, v3;
        v0.x = u[i][0].x - u[i][2].x;  v0.y = u[i][0].y - u[i][2].y;
        v1.x = u[i][1].x + u[i][2].x;  v1.y = u[i][1].y + u[i][2].y;
        v2.x = u[i][2].x - u[i][1].x;  v2.y = u[i][2].y - u[i][1].y;
        v3.x = u[i][1].x - u[i][3].x;  v3.y = u[i][1].y - u[i][3].y;
        size_t base = (size_t)t * 512 + ci;
        *(__half2*)&g_V[(size_t)(i * 4 + 0) * (NT * CI) + base] = __floats2half2_rn(v0.x, v0.y);
        *(__half2*)&g_V[(size_t)(i * 4 + 1) * (NT * CI) + base] = __floats2half2_rn(v1.x, v1.y);
        *(__half2*)&g_V[(size_t)(i * 4 + 2) * (NT * CI) + base] = __floats2half2_rn(v2.x, v2.y);
        *(__half2*)&g_V[(size_t)(i * 4 + 3) * (NT * CI) + base] = __floats2half2_rn(v3.x, v3.y);
    }
}

// ---------------- Winograd-domain GEMM ----------------
__device__ __forceinline__ uint32_t s2u(const void* p) {
    return (uint32_t)__cvta_generic_to_shared(p);
}
__device__ __forceinline__ void ldsm4(uint32_t* r, uint32_t a) {
    asm volatile("ldmatrix.sync.aligned.m8n8.x4.shared.b16 {%0,%1,%2,%3}, [%4];"
                 : "=r"(r[0]), "=r"(r[1]), "=r"(r[2]), "=r"(r[3]) : "r"(a));
}
__device__ __forceinline__ void mma16816(float* c, const uint32_t* a, uint32_t b0, uint32_t b1) {
    asm volatile("mma.sync.aligned.m16n8k16.row.col.f32.f16.f16.f32 "
                 "{%0,%1,%2,%3}, {%4,%5,%6,%7}, {%8,%9}, {%0,%1,%2,%3};"
                 : "+f"(c[0]), "+f"(c[1]), "+f"(c[2]), "+f"(c[3])
                 : "r"(a[0]), "r"(a[1]), "r"(a[2]), "r"(a[3]), "r"(b0), "r"(b1));
}
__device__ __forceinline__ void cpa16(uint32_t d, const void* s) {
    asm volatile("cp.async.cg.shared.global [%0], [%1], 16;"
                 :: "r"(d), "l"(s) : "memory");
}
__device__ __forceinline__ void cp_commit() {
    asm volatile("cp.async.commit_group;" ::: "memory");
}
__device__ __forceinline__ void cp_wait1() {
    asm volatile("cp.async.wait_group 1;" ::: "memory");
}

// stage = A(64 o x 80B) + B(256 t x 80B); ring of 3. Epilogue staging tile
// overlays the same smem: 256 t x 72 halves = 36864 B <= 76800 B.
#define GA_BUF 5120
#define GB_BUF 20480
#define GSTAGE (GA_BUF + GB_BUF)
#define GSM_TOTAL (3 * GSTAGE)

// CTA = 64 o x 256 tiles, one Winograd point. grid (8 ob, 32 tb, 16 p).
__global__ __launch_bounds__(256, 2) void k_wgemm() {
    extern __shared__ char smraw[];
    int tid = threadIdx.x, lane = tid & 31, warp = tid >> 5;
    int wm = warp & 1, wn = warp >> 1;
    int ob = blockIdx.x, tb = blockIdx.y, p = blockIdx.z;

    const __half* U = g_U + (size_t)p * (CO * CI) + (size_t)(ob * 64) * 512;
    const __half* V = g_V + (size_t)p * (NT * CI) + (size_t)(tb * 256) * 512;
    __half* M = g_M + (size_t)p * (NT * CO) + (size_t)(tb * 256) * 512 + ob * 64;

    float acc[2][2][4][4];
#pragma unroll
    for (int i = 0; i < 2; i++)
#pragma unroll
        for (int g = 0; g < 2; g++)
#pragma unroll
            for (int j = 0; j < 4; j++)
#pragma unroll
                for (int k = 0; k < 4; k++) acc[i][g][j][k] = 0.f;

    auto issue = [&](int c) {
        char* st = smraw + (c % 3) * GSTAGE;
        {   // A: 64 rows x 4 chunks = 256
            int row = tid >> 2, q = tid & 3;
            cpa16(s2u(st + row * 80 + q * 16), U + (size_t)row * 512 + c * 32 + q * 8);
        }
#pragma unroll
        for (int k = 0; k < 4; k++) {  // B: 256 rows x 4 chunks = 1024
            int idx = tid + 256 * k;
            int row = idx >> 2, q = idx & 3;
            cpa16(s2u(st + GA_BUF + row * 80 + q * 16), V + (size_t)row * 512 + c * 32 + q * 8);
        }
    };

    issue(0); cp_commit();
    issue(1); cp_commit();

    uint32_t aLane = (uint32_t)((wm * 32 + (lane & 15)) * 80 + ((lane >> 4) << 4));

    for (int c = 0; c < 16; ++c) {
        cp_wait1();
        __syncthreads();
        if (c + 2 < 16) issue(c + 2);
        cp_commit();

        char* st = smraw + (c % 3) * GSTAGE;
        uint32_t aB = s2u(st) + aLane;
        uint32_t bBase = s2u(st + GA_BUF);

        uint32_t a[2][2][4];
        ldsm4(a[0][0], aB);
        ldsm4(a[0][1], aB + 16 * 80);
        ldsm4(a[1][0], aB + 32);
        ldsm4(a[1][1], aB + 16 * 80 + 32);

#pragma unroll
        for (int g = 0; g < 2; g++) {
            uint32_t ba = bBase + (uint32_t)((wn * 64 + g * 32 + lane) * 80);
#pragma unroll
            for (int k0 = 0; k0 < 2; k0++) {
                uint32_t pr[4], qr[4];
                ldsm4(pr, ba + k0 * 32);
                ldsm4(qr, ba + k0 * 32 + 16);
#pragma unroll
                for (int j = 0; j < 4; j++) {
                    mma16816(acc[0][g][j], a[k0][0], pr[j], qr[j]);
                    mma16816(acc[1][g][j], a[k0][1], pr[j], qr[j]);
                }
            }
        }
    }

    // ---- epilogue: fp16 M, staged via smem for coalesced stores ----
    __syncthreads();                       // all warps done with stage buffers
    __half* MT = (__half*)smraw;           // [256 t][72] halves
#pragma unroll
    for (int i = 0; i < 2; i++) {
        int o = wm * 32 + i * 16 + (lane >> 2);
#pragma unroll
        for (int g = 0; g < 2; g++) {
#pragma unroll
            for (int j = 0; j < 4; j++) {
                int tl = wn * 64 + g * 32 + j * 8 + (lane & 3) * 2;
                MT[tl * 72 + o]           = __float2half_rn(acc[i][g][j][0]);
                MT[(tl + 1) * 72 + o]     = __float2half_rn(acc[i][g][j][1]);
                MT[tl * 72 + o + 8]       = __float2half_rn(acc[i][g][j][2]);
                MT[(tl + 1) * 72 + o + 8] = __float2half_rn(acc[i][g][j][3]);
            }
        }
    }
    __syncthreads();
#pragma unroll
    for (int it = 0; it < 8; it++) {       // 256 t x 64 o: 2048 x 16B chunks
        int idx = tid + 256 * it;
        int t = idx >> 3, ch = idx & 7;
        uint4 v = *(uint4*)&MT[t * 72 + ch * 8];
        *(uint4*)&M[(size_t)t * 512 + ch * 8] = v;
    }
}

// inverse transform + demod + NCHW store. grid (16 ob, 32 ty, 8 b), 256 thr.
__global__ void k_wino_out(float* __restrict__ out) {
    __shared__ float sm[32][2][64];
    int ob = blockIdx.x, ty = blockIdx.y, b = blockIdx.z;
    int tid = threadIdx.x;
    int og = tid & 7, tx = tid >> 3;
    int t = (b << 10) + (ty << 5) + tx;
    int o0 = ob * 32 + og * 4;

    float m[16][4];
#pragma unroll
    for (int p = 0; p < 16; p++) {
        uint2 raw = *(const uint2*)&g_M[(size_t)p * (NT * CO) + (size_t)t * 512 + o0];
        __half2 h0 = *(__half2*)&raw.x;
        __half2 h1 = *(__half2*)&raw.y;
        float2 f0 = __half22float2(h0);
        float2 f1 = __half22float2(h1);
        m[p][0] = f0.x; m[p][1] = f0.y; m[p][2] = f1.x; m[p][3] = f1.y;
    }
#pragma unroll
    for (int k = 0; k < 4; k++) {
        float ds = g_d[b * 512 + o0 + k];
        float r0[4], r1[4];
#pragma unroll
        for (int j = 0; j < 4; j++) {
            r0[j] = m[0 * 4 + j][k] + m[1 * 4 + j][k] + m[2 * 4 + j][k];
            r1[j] = m[1 * 4 + j][k] - m[2 * 4 + j][k] - m[3 * 4 + j][k];
        }
        int ol = og * 4 + k;
        sm[ol][0][2 * tx]     = (r0[0] + r0[1] + r0[2]) * ds;
        sm[ol][0][2 * tx + 1] = (r0[1] - r0[2] - r0[3]) * ds;
        sm[ol][1][2 * tx]     = (r1[0] + r1[1] + r1[2]) * ds;
        sm[ol][1][2 * tx + 1] = (r1[1] - r1[2] - r1[3]) * ds;
    }
    __syncthreads();
#pragma unroll
    for (int k = 0; k < 4; k++) {
        int idx = tid + 256 * k;
        int w4 = idx & 15, dy = (idx >> 4) & 1, ol = idx >> 5;
        float4 v = *(const float4*)&sm[ol][dy][w4 * 4];
        *(float4*)&out[(((size_t)(b * 512 + ob * 32 + ol)) * 64 + 2 * ty + dy) * 64 + w4 * 4] = v;
    }
}

// ---------------- launcher ----------------
extern "C" void kernel_launch(void* const* d_in, const int* in_sizes, int n_in,
                              void* d_out, int out_size) {
    const float* x  = (const float*)d_in[0];
    const float* dl = (const float*)d_in[1];
    const float* w  = (const float*)d_in[2];
    const float* dw = (const float*)d_in[3];
    const float* db = (const float*)d_in[4];
    float* out = (float*)d_out;

    k_style<<<16, 256>>>(dl, dw, db);
    k_wino_w<<<1024, 256>>>(w);
    k_demod<<<16, 256>>>();
    k_xs_nhwc<<<dim3(16, 64, 8), 256>>>(x);
    k_wino_in<<<8192, 256>>>();

    cudaFuncSetAttribute(k_wgemm, cudaFuncAttributeMaxDynamicSharedMemorySize, GSM_TOTAL);
    k_wgemm<<<dim3(8, 32, 16), 256, GSM_TOTAL>>>();

    k_wino_out<<<dim3(16, 32, 8), 256>>>(out);
}